// round 4
// baseline (speedup 1.0000x reference)
#include <cuda_runtime.h>
#include <math.h>

#define BB   64
#define LQV  20
#define LDV  512
#define DV   300
#define EQV  5
#define EDV  10
#define DESCV 20
#define KCV  10

// merged-GEMM block ranges
#define NB_QW   120    // 20 blocks x 6 slices
#define NB_DW   3072   // 512 x 6
#define NB_QD   500    // 100 x 5
#define NB_DD   1000   // 200 x 5
#define NB_ALL  (NB_QW + NB_DW + NB_QD + NB_DD)

// ---------------- constants ----------------
__constant__ float c_MU[11]  = {1.0f,0.9f,0.7f,0.5f,0.3f,0.1f,-0.1f,-0.3f,-0.5f,-0.7f,-0.9f};
__constant__ float c_IS2[11] = {500000.0f,50.f,50.f,50.f,50.f,50.f,50.f,50.f,50.f,50.f,50.f};
// pool order from reference: (qtype, dtype), types: 0=uni 1=bi 2=tri 3=ent
__constant__ int c_poolQ[16] = {0,0,0,1,2,1,1,2,2,3,3,3,0,1,2,3};
__constant__ int c_poolD[16] = {0,2,1,0,0,1,2,1,2,0,1,2,3,3,3,3};

// ---------------- scratch (device globals; no allocations allowed) --------
__device__ float g_Wt_word[6*300*128];   // transposed word conv slices [slice][k][n]
__device__ float g_Wt_desc[5*300*128];   // transposed desc conv slices
__device__ float g_Yq[BB*LQV*768];
__device__ float g_Yd[(size_t)BB*LDV*768];
__device__ float g_Ydesc[(size_t)19200*640];   // 6400 q-rows then 12800 d-rows
__device__ float g_qu[BB*20*128];
__device__ float g_qb[BB*19*128];
__device__ float g_qt[BB*18*128];
__device__ float g_du[(size_t)BB*512*128];
__device__ float g_db[(size_t)BB*511*128];
__device__ float g_dt[(size_t)BB*510*128];
__device__ float g_qs[BB*5*128];
__device__ float g_ds[BB*10*128];
__device__ float g_sump[2*BB*4*300];     // partial embedding sums
__device__ float g_bow[2*BB*128];        // [0..63]=q bow, [64..127]=d bow
__device__ float g_feats[BB*176];

// ---------------- helpers ----------------
__device__ __forceinline__ float block_sum_128(float v) {
    __shared__ float sh[4];
    v += __shfl_down_sync(0xffffffffu, v, 16);
    v += __shfl_down_sync(0xffffffffu, v, 8);
    v += __shfl_down_sync(0xffffffffu, v, 4);
    v += __shfl_down_sync(0xffffffffu, v, 2);
    v += __shfl_down_sync(0xffffffffu, v, 1);
    if ((threadIdx.x & 31) == 0) sh[threadIdx.x >> 5] = v;
    __syncthreads();
    float r = sh[0] + sh[1] + sh[2] + sh[3];
    __syncthreads();
    return r;
}

__device__ __forceinline__ unsigned long long pack_dup(float a) {
    unsigned long long r;
    asm("mov.b64 %0, {%1, %1};" : "=l"(r) : "r"(__float_as_uint(a)));
    return r;
}
__device__ __forceinline__ void ffma2(unsigned long long& d,
                                      unsigned long long a, unsigned long long b) {
    asm("fma.rn.f32x2 %0, %1, %2, %0;" : "+l"(d) : "l"(a), "l"(b));
}
__device__ __forceinline__ void unpack2(unsigned long long v, float& lo, float& hi) {
    asm("mov.b64 {%0, %1}, %2;" : "=f"(lo), "=f"(hi) : "l"(v));
}

// ---------------- weight transpose ----------------
__global__ void k_prep_weights(const float* uW, const float* bW, const float* tW, const float* dW) {
    int stride = gridDim.x * blockDim.x;
    for (int e = blockIdx.x*blockDim.x + threadIdx.x; e < 6*300*128; e += stride) {
        int s = e / (300*128); int r = e % (300*128); int k = r >> 7; int n = r & 127;
        float v;
        if (s == 0)      v = uW[n*300 + k];
        else if (s <= 2) v = bW[n*600 + (s-1)*300 + k];
        else             v = tW[n*900 + (s-3)*300 + k];
        g_Wt_word[e] = v;
    }
    for (int e = blockIdx.x*blockDim.x + threadIdx.x; e < 5*300*128; e += stride) {
        int i = e / (300*128); int r = e % (300*128); int k = r >> 7; int n = r & 127;
        g_Wt_desc[e] = dW[n*1500 + i*300 + k];
    }
}

// ---------------- partial embedding sums (for bow) ----------------
__global__ void k_sum_part(const int* qwt, const int* dwt, const float* emb) {
    int dim = threadIdx.x; if (dim >= 300) return;
    int b = blockIdx.x; int isD = blockIdx.y; int sl = blockIdx.z;
    const int* tok; int L;
    if (isD) { tok = dwt + b*LDV; L = LDV; } else { tok = qwt + b*LQV; L = LQV; }
    int per = (L + 3) >> 2;
    int l0 = sl * per; int l1 = min(L, l0 + per);
    float s0 = 0.f, s1 = 0.f, s2 = 0.f, s3 = 0.f;
    int l = l0;
    for (; l + 4 <= l1; l += 4) {
        s0 += emb[(size_t)tok[l  ]*300 + dim];
        s1 += emb[(size_t)tok[l+1]*300 + dim];
        s2 += emb[(size_t)tok[l+2]*300 + dim];
        s3 += emb[(size_t)tok[l+3]*300 + dim];
    }
    for (; l < l1; l++) s0 += emb[(size_t)tok[l]*300 + dim];
    g_sump[(((isD*BB) + b)*4 + sl)*300 + dim] = s0 + s1 + s2 + s3;
}

// ---------------- bow projection ----------------
__global__ void k_bow(const float* bow_W, const float* bow_b) {
    int b = blockIdx.x, isD = blockIdx.y, o = threadIdx.x;
    __shared__ float s[300];
    const float* base = g_sump + ((size_t)(isD*BB) + b)*4*300;
    for (int i = o; i < 300; i += 128)
        s[i] = base[i] + base[300+i] + base[600+i] + base[900+i];
    __syncthreads();
    float acc = 0.f;
    const float* w = bow_W + o*300;
    #pragma unroll 4
    for (int k = 0; k < 300; k++) acc = fmaf(s[k], w[k], acc);
    int L = isD ? LDV : LQV;
    g_bow[(isD*BB + b)*128 + o] = acc + (float)L * bow_b[o];
}

// ---------------- merged gathered GEMM --------------------------------------
// One launch covers all four token GEMMs: Y[m, s*128+n] = emb[tok[m]] . Wt[s][:,n]
// 128 threads / block, 64x128 tile, per-thread 8 rows x 8 cols, columns packed
// in f32x2 lanes (fma.rn.f32x2 = 2 MACs/issue).
__global__ void __launch_bounds__(128) k_gemm_all(const int* qwt, const int* dwt,
                                                  const int* qet, const int* det,
                                                  const float* emb) {
    int blk = blockIdx.x;
    const int* tokens; const float* Wt_base; float* Y; int ldY, s, mb;
    if (blk < NB_QW) {
        s = blk / 20; mb = blk % 20;
        tokens = qwt; Wt_base = g_Wt_word; Y = g_Yq; ldY = 768;
    } else if (blk < NB_QW + NB_DW) {
        int r = blk - NB_QW; s = r / 512; mb = r % 512;
        tokens = dwt; Wt_base = g_Wt_word; Y = g_Yd; ldY = 768;
    } else if (blk < NB_QW + NB_DW + NB_QD) {
        int r = blk - (NB_QW + NB_DW); s = r / 100; mb = r % 100;
        tokens = qet; Wt_base = g_Wt_desc; Y = g_Ydesc; ldY = 640;
    } else {
        int r = blk - (NB_QW + NB_DW + NB_QD); s = r / 200; mb = r % 200;
        tokens = det; Wt_base = g_Wt_desc; Y = g_Ydesc + (size_t)BB*EQV*DESCV*640; ldY = 640;
    }

    const float* Wt = Wt_base + (size_t)s*300*128;
    int m0 = mb * 64;
    __shared__ float As[20][68];       // padded rows keep 16B alignment per kk
    __shared__ float Bs[20][128];
    __shared__ int   toks[64];
    int t = threadIdx.x;
    if (t < 64) toks[t] = tokens[m0 + t];
    __syncthreads();

    unsigned long long c2[8][4];
    #pragma unroll
    for (int r = 0; r < 8; r++)
        #pragma unroll
        for (int n = 0; n < 4; n++) c2[r][n] = 0ull;

    int tc = t & 15, tr = t >> 4;      // 16 col-groups x 8 row-groups
    int r0 = tr * 8, c0 = tc * 8;
    int arow = t >> 1;                 // 64 rows, 2 threads per row
    int aks  = (t & 1) * 10;
    const float* abase = emb + (size_t)toks[arow]*300 + aks;

    for (int k0 = 0; k0 < 300; k0 += 20) {
        #pragma unroll
        for (int j = 0; j < 10; j++) As[aks + j][arow] = abase[k0 + j];
        #pragma unroll
        for (int i = 0; i < 20; i++) Bs[i][t] = Wt[(size_t)(k0 + i)*128 + t];
        __syncthreads();
        #pragma unroll
        for (int kk = 0; kk < 20; kk++) {
            float4 a0 = *(const float4*)&As[kk][r0];
            float4 a1 = *(const float4*)&As[kk][r0 + 4];
            ulonglong2 b01 = *(const ulonglong2*)&Bs[kk][c0];
            ulonglong2 b23 = *(const ulonglong2*)&Bs[kk][c0 + 4];
            unsigned long long bv0 = b01.x, bv1 = b01.y, bv2 = b23.x, bv3 = b23.y;
            float av[8] = {a0.x,a0.y,a0.z,a0.w,a1.x,a1.y,a1.z,a1.w};
            #pragma unroll
            for (int r = 0; r < 8; r++) {
                unsigned long long aa = pack_dup(av[r]);
                ffma2(c2[r][0], aa, bv0);
                ffma2(c2[r][1], aa, bv1);
                ffma2(c2[r][2], aa, bv2);
                ffma2(c2[r][3], aa, bv3);
            }
        }
        __syncthreads();
    }
    #pragma unroll
    for (int r = 0; r < 8; r++) {
        float o0,o1,o2,o3,o4,o5,o6,o7;
        unpack2(c2[r][0], o0, o1);
        unpack2(c2[r][1], o2, o3);
        unpack2(c2[r][2], o4, o5);
        unpack2(c2[r][3], o6, o7);
        float* dst = &Y[(size_t)(m0 + r0 + r)*ldY + s*128 + c0];
        *(float4*)dst       = make_float4(o0, o1, o2, o3);
        *(float4*)(dst + 4) = make_float4(o4, o5, o6, o7);
    }
}

// ---------------- combine conv slices + relu + l2 normalize ----------------
// ISD: 0 = query (L=20, out g_qu/g_qb/g_qt), 1 = doc (L=512, out g_du/g_db/g_dt)
template<int ISD>
__global__ void k_combine(const float* ub, const float* bbias, const float* tb) {
    const float* Y = ISD ? g_Yd : g_Yq;
    float* outU = ISD ? g_du : g_qu;
    float* outB = ISD ? g_db : g_qb;
    float* outT = ISD ? g_dt : g_qt;
    const int L = ISD ? LDV : LQV;

    int idx = blockIdx.x;
    int l = idx % L;
    int o = threadIdx.x;
    const float* y0 = Y + (size_t)idx * 768;
    float u = fmaxf(y0[o] + ub[o], 0.f);
    bool hasB = (l < L-1), hasT = (l < L-2);
    float bv = 0.f, tv = 0.f;
    if (hasB) bv = fmaxf(y0[128+o] + y0[768+256+o] + bbias[o], 0.f);
    if (hasT) tv = fmaxf(y0[384+o] + y0[768+512+o] + y0[1536+640+o] + tb[o], 0.f);
    float su = block_sum_128(u*u);
    float sb = block_sum_128(bv*bv);
    float st = block_sum_128(tv*tv);
    int b = idx / L;
    outU[(size_t)idx*128 + o] = u / fmaxf(sqrtf(su), 1e-10f);
    if (hasB) outB[((size_t)b*(L-1) + l)*128 + o] = bv / fmaxf(sqrtf(sb), 1e-10f);
    if (hasT) outT[((size_t)b*(L-2) + l)*128 + o] = tv / fmaxf(sqrtf(st), 1e-10f);
}

// ---------------- entity branch ----------------
__global__ void k_ent(const int* qei, const int* qew, const int* dei, const int* dew,
                      const float* ent_emb, const float* car_emb, const float* des_b) {
    int x = blockIdx.x;            // 0..959 : first 320 q entities, then 640 d entities
    bool isQ = x < BB*EQV;
    int o = threadIdx.x;           // 128
    int b, e, rowbase, eid;
    const int* carIds; const float* bow;
    if (isQ) {
        b = x / EQV; e = x % EQV;
        rowbase = x * DESCV;
        carIds = qew + b*EQV*KCV + e*KCV;
        eid = qei[b*EQV + e];
        bow = g_bow + (size_t)b*128;
    } else {
        int xi = x - BB*EQV;
        b = xi / EDV; e = xi % EDV;
        rowbase = BB*EQV*DESCV + xi*DESCV;
        carIds = dew + b*EDV*KCV + e*KCV;
        eid = dei[b*EDV + e];
        bow = g_bow + (size_t)(BB + b)*128;
    }
    // desc conv + max pool (relu >= 0 so init 0 is the identity for max-of-relu)
    float bias = des_b[o];
    float mx = 0.f;
    for (int pos = 0; pos < 16; pos++) {
        float sacc = bias;
        #pragma unroll
        for (int i = 0; i < 5; i++)
            sacc += g_Ydesc[(size_t)(rowbase + pos + i)*640 + i*128 + o];
        mx = fmaxf(mx, sacc);
    }
    __shared__ float bs[128];
    __shared__ float tS[10][128];
    __shared__ float sc[10];
    __shared__ float att[10];
    bs[o] = bow[o];
    __syncthreads();
    for (int k = 0; k < 10; k++) {
        float v = car_emb[(size_t)carIds[k]*128 + o];
        tS[k][o] = v;
        float p = block_sum_128(bs[o] * v);
        if (o == 0) sc[k] = p;
    }
    __syncthreads();
    if (o == 0) {
        float m = sc[0];
        #pragma unroll
        for (int k = 1; k < 10; k++) m = fmaxf(m, sc[k]);
        float sum = 0.f;
        #pragma unroll
        for (int k = 0; k < 10; k++) { att[k] = expf(sc[k] - m); sum += att[k]; }
        float inv = 1.f / sum;
        #pragma unroll
        for (int k = 0; k < 10; k++) att[k] *= inv;
    }
    __syncthreads();
    float ew = 0.f;
    #pragma unroll
    for (int k = 0; k < 10; k++) ew = fmaf(att[k], tS[k][o], ew);
    float val = ent_emb[(size_t)eid*128 + o] + mx + ew;
    float nsq = block_sum_128(val * val);
    float nv = val / fmaxf(sqrtf(nsq), 1e-10f);
    if (isQ) g_qs[(size_t)(b*EQV + e)*128 + o] = nv;
    else     g_ds[(size_t)(b*EDV + e)*128 + o] = nv;
}

// ---------------- kernel pooling (one block per (batch, pool)) -------------
__global__ void __launch_bounds__(256) k_pool(const float* qwm, const float* qem,
                                              const float* dwm, const float* dem) {
    int blk = blockIdx.x;
    int b = blk >> 4, p = blk & 15;
    int qt = c_poolQ[p], dt = c_poolD[p];

    const float* Q; int Lq; const float* mqp;
    switch (qt) {
        case 0: Q = g_qu + (size_t)b*20*128; Lq = 20; mqp = qwm + b*LQV; break;
        case 1: Q = g_qb + (size_t)b*19*128; Lq = 19; mqp = qwm + b*LQV; break;
        case 2: Q = g_qt + (size_t)b*18*128; Lq = 18; mqp = qwm + b*LQV; break;
        default:Q = g_qs + (size_t)b*5*128;  Lq = 5;  mqp = qem + b*EQV; break;
    }
    const float* Dp; int Ld; const float* mdp;
    switch (dt) {
        case 0: Dp = g_du + (size_t)b*512*128; Ld = 512; mdp = dwm + b*LDV; break;
        case 1: Dp = g_db + (size_t)b*511*128; Ld = 511; mdp = dwm + b*LDV; break;
        case 2: Dp = g_dt + (size_t)b*510*128; Ld = 510; mdp = dwm + b*LDV; break;
        default:Dp = g_ds + (size_t)b*10*128;  Ld = 10;  mdp = dem + b*EDV; break;
    }

    __shared__ float Qs[20][132];
    __shared__ float DtS[128][36];
    __shared__ float simS[20][36];
    __shared__ float mdS[32];
    __shared__ float lpsS[20*11];

    int t = threadIdx.x;
    for (int e = t; e < Lq*128; e += 256) { int q = e >> 7, k = e & 127; Qs[q][k] = Q[e]; }

    int myq = t / 11, myk = t % 11;
    bool active = t < Lq * 11;
    float mu_ = c_MU[myk], is2 = c_IS2[myk];
    float acc = 0.f;

    for (int cc0 = 0; cc0 < Ld; cc0 += 32) {
        int cn = min(32, Ld - cc0);
        __syncthreads();                          // prev phase-B done before Dt reload
        for (int e = t; e < cn*128; e += 256) {
            int cc = e >> 7, k = e & 127;
            DtS[k][cc] = Dp[(size_t)(cc0 + cc)*128 + k];
        }
        if (t < cn) mdS[t] = mdp[cc0 + t];
        __syncthreads();
        int ncg = (cn + 3) >> 2;
        for (int mt = t; mt < Lq*8; mt += 256) {
            int q = mt >> 3, cg = mt & 7;
            if (cg < ncg) {
                float s0 = 0.f, s1 = 0.f, s2 = 0.f, s3 = 0.f;
                const float* qrow = &Qs[q][0];
                #pragma unroll 4
                for (int kk = 0; kk < 128; kk++) {
                    float qa = qrow[kk];
                    float4 d4 = *(const float4*)&DtS[kk][cg << 2];
                    s0 = fmaf(qa, d4.x, s0);
                    s1 = fmaf(qa, d4.y, s1);
                    s2 = fmaf(qa, d4.z, s2);
                    s3 = fmaf(qa, d4.w, s3);
                }
                int cb = cg << 2;
                simS[q][cb] = s0; simS[q][cb+1] = s1; simS[q][cb+2] = s2; simS[q][cb+3] = s3;
            }
        }
        __syncthreads();
        if (active) {
            const float* srow = &simS[myq][0];
            for (int cc = 0; cc < cn; cc++) {
                float df = srow[cc] - mu_;
                acc = fmaf(mdS[cc], expf(-df*df*is2), acc);
            }
        }
    }
    __syncthreads();
    if (active)
        lpsS[myq*11 + myk] = logf(fmaxf(acc, 1e-10f)) * 0.01f * mqp[myq];
    __syncthreads();
    if (t < 11) {
        float s = 0.f;
        for (int q = 0; q < Lq; q++) s += lpsS[q*11 + t];
        g_feats[b*176 + p*11 + t] = s;
    }
}

// ---------------- final dense + tanh ----------------
__global__ void k_final(const float* W, const float* b0, float* out) {
    int b = threadIdx.x;
    if (b < BB) {
        float s = b0[0];
        #pragma unroll 4
        for (int j = 0; j < 176; j++) s = fmaf(g_feats[b*176 + j], W[j], s);
        out[b] = tanhf(s);
    }
}

// ---------------- launch ----------------
extern "C" void kernel_launch(void* const* d_in, const int* in_sizes, int n_in,
                              void* d_out, int out_size) {
    const int*   qwt  = (const int*)  d_in[0];
    const float* qwm  = (const float*)d_in[1];
    const int*   qei  = (const int*)  d_in[2];
    const int*   qet  = (const int*)  d_in[3];
    const int*   qew  = (const int*)  d_in[4];
    const float* qem  = (const float*)d_in[5];
    const int*   dwt  = (const int*)  d_in[6];
    const float* dwm  = (const float*)d_in[7];
    const int*   dei  = (const int*)  d_in[8];
    const int*   det  = (const int*)  d_in[9];
    const int*   dew  = (const int*)  d_in[10];
    const float* dem  = (const float*)d_in[11];
    const float* wrd  = (const float*)d_in[12];
    const float* ente = (const float*)d_in[13];
    const float* care = (const float*)d_in[14];
    const float* bowW = (const float*)d_in[15];
    const float* bowb = (const float*)d_in[16];
    const float* uW   = (const float*)d_in[17];
    const float* ub   = (const float*)d_in[18];
    const float* bW   = (const float*)d_in[19];
    const float* bb   = (const float*)d_in[20];
    const float* tW   = (const float*)d_in[21];
    const float* tb   = (const float*)d_in[22];
    const float* dW   = (const float*)d_in[23];
    const float* db_  = (const float*)d_in[24];
    const float* fW   = (const float*)d_in[25];
    const float* fb   = (const float*)d_in[26];
    float* out = (float*)d_out;

    k_prep_weights<<<240, 256>>>(uW, bW, tW, dW);
    k_sum_part<<<dim3(BB, 2, 4), 320>>>(qwt, dwt, wrd);
    k_bow<<<dim3(BB, 2), 128>>>(bowW, bowb);

    k_gemm_all<<<NB_ALL, 128>>>(qwt, dwt, qet, det, wrd);

    k_combine<0><<<BB*LQV, 128>>>(ub, bb, tb);
    k_combine<1><<<BB*LDV, 128>>>(ub, bb, tb);

    k_ent<<<BB*(EQV + EDV), 128>>>(qei, qew, dei, dew, ente, care, db_);
    k_pool<<<BB*16, 256>>>(qwm, qem, dwm, dem);
    k_final<<<1, 64>>>(fW, fb, out);
}

// round 11
// speedup vs baseline: 1.4757x; 1.4757x over previous
#include <cuda_runtime.h>
#include <cuda_bf16.h>
#include <stdint.h>
#include <math.h>

#define BB   64
#define LQV  20
#define LDV  512
#define DV   300
#define EQV  5
#define EDV  10
#define DESCV 20
#define KCV  10

// ---------------- GEMM geometry ----------------
#define KPAD      320              // 5 chunks x 64 bf16
#define NCHUNK    5
#define NSLICES   11               // 6 word + 5 desc
#define TB_QW 60                   // 10 tiles x 6 slices
#define TB_DW 1536                 // 256 x 6
#define TB_QD 250                  // 50 x 5
#define TB_DD 500                  // 100 x 5
#define TB_ALL (TB_QW + TB_DW + TB_QD + TB_DD)   // 2346

// dynamic smem layout (bytes). A/B tiles 128 rows x 64 k bf16, row pitch 72
// bf16 = 144 B (conflict-free frag loads: bank = (36r + t') mod 32 = lane).
#define APITCH    144
#define OFF_TOKS  0                // 128 ints
#define OFF_AHI   512
#define OFF_ALO   (OFF_AHI + 128*APITCH)   // 18944
#define OFF_BHI   (OFF_ALO + 128*APITCH)   // 37376
#define OFF_BLO   (OFF_BHI + 128*APITCH)   // 55808
#define SMEM_DYN  (OFF_BLO + 128*APITCH)   // 74240

// ---------------- constants ----------------
__constant__ float c_MU[11]  = {1.0f,0.9f,0.7f,0.5f,0.3f,0.1f,-0.1f,-0.3f,-0.5f,-0.7f,-0.9f};
__constant__ float c_IS2[11] = {500000.0f,50.f,50.f,50.f,50.f,50.f,50.f,50.f,50.f,50.f,50.f};
__constant__ int c_poolQ[16] = {0,0,0,1,2,1,1,2,2,3,3,3,0,1,2,3};
__constant__ int c_poolD[16] = {0,2,1,0,0,1,2,1,2,0,1,2,3,3,3,3};

// ---------------- scratch ----------------
__device__ __nv_bfloat16 g_WbH[NSLICES*128*KPAD];   // weights bf16 hi [slice][n][k]
__device__ __nv_bfloat16 g_WbL[NSLICES*128*KPAD];   // weights bf16 lo
__device__ float g_Yq[BB*LQV*768];
__device__ float g_Yd[(size_t)BB*LDV*768];
__device__ float g_Ydesc[(size_t)19200*640];
__device__ float g_qu[BB*20*128];
__device__ float g_qb[BB*19*128];
__device__ float g_qt[BB*18*128];
__device__ float g_du[(size_t)BB*512*128];
__device__ float g_db[(size_t)BB*511*128];
__device__ float g_dt[(size_t)BB*510*128];
__device__ float g_qs[BB*5*128];
__device__ float g_ds[BB*10*128];
__device__ float g_sump[2*BB*4*300];
__device__ float g_bow[2*BB*128];
__device__ float g_feats[BB*176];

// ---------------- helpers ----------------
__device__ __forceinline__ void mma_bf16(float* c, const uint32_t* a,
                                         uint32_t b0, uint32_t b1) {
    asm volatile("mma.sync.aligned.m16n8k16.row.col.f32.bf16.bf16.f32 "
        "{%0,%1,%2,%3}, {%4,%5,%6,%7}, {%8,%9}, {%0,%1,%2,%3};"
        : "+f"(c[0]), "+f"(c[1]), "+f"(c[2]), "+f"(c[3])
        : "r"(a[0]), "r"(a[1]), "r"(a[2]), "r"(a[3]), "r"(b0), "r"(b1));
}

__device__ __forceinline__ float block_sum_128(float v) {
    __shared__ float sh[4];
    v += __shfl_down_sync(0xffffffffu, v, 16);
    v += __shfl_down_sync(0xffffffffu, v, 8);
    v += __shfl_down_sync(0xffffffffu, v, 4);
    v += __shfl_down_sync(0xffffffffu, v, 2);
    v += __shfl_down_sync(0xffffffffu, v, 1);
    if ((threadIdx.x & 31) == 0) sh[threadIdx.x >> 5] = v;
    __syncthreads();
    float r = sh[0] + sh[1] + sh[2] + sh[3];
    __syncthreads();
    return r;
}

// ---------------- weight prep: fp32 -> bf16 hi/lo, [slice][n][kpad] ----------
__global__ void k_prep_weights(const float* uW, const float* bW, const float* tW, const float* dW) {
    int stride = gridDim.x * blockDim.x;
    for (int e = blockIdx.x*blockDim.x + threadIdx.x; e < NSLICES*128*KPAD; e += stride) {
        int s = e / (128*KPAD); int r = e % (128*KPAD); int n = r / KPAD; int k = r % KPAD;
        float v = 0.f;
        if (k < 300) {
            if (s == 0)      v = uW[n*300 + k];
            else if (s <= 2) v = bW[n*600 + (s-1)*300 + k];
            else if (s <= 5) v = tW[n*900 + (s-3)*300 + k];
            else             v = dW[n*1500 + (s-6)*300 + k];
        }
        __nv_bfloat16 h = __float2bfloat16(v);
        __nv_bfloat16 l = __float2bfloat16(v - __bfloat162float(h));
        g_WbH[e] = h; g_WbL[e] = l;
    }
}

// ---------------- partial embedding sums (for bow) ----------------
__global__ void k_sum_part(const int* qwt, const int* dwt, const float* emb) {
    int dim = threadIdx.x; if (dim >= 300) return;
    int b = blockIdx.x; int isD = blockIdx.y; int sl = blockIdx.z;
    const int* tok; int L;
    if (isD) { tok = dwt + b*LDV; L = LDV; } else { tok = qwt + b*LQV; L = LQV; }
    int per = (L + 3) >> 2;
    int l0 = sl * per; int l1 = min(L, l0 + per);
    float s0 = 0.f, s1 = 0.f, s2 = 0.f, s3 = 0.f;
    int l = l0;
    for (; l + 4 <= l1; l += 4) {
        s0 += emb[(size_t)tok[l  ]*300 + dim];
        s1 += emb[(size_t)tok[l+1]*300 + dim];
        s2 += emb[(size_t)tok[l+2]*300 + dim];
        s3 += emb[(size_t)tok[l+3]*300 + dim];
    }
    for (; l < l1; l++) s0 += emb[(size_t)tok[l]*300 + dim];
    g_sump[(((isD*BB) + b)*4 + sl)*300 + dim] = s0 + s1 + s2 + s3;
}

// ---------------- bow projection ----------------
__global__ void k_bow(const float* bow_W, const float* bow_b) {
    int b = blockIdx.x, isD = blockIdx.y, o = threadIdx.x;
    __shared__ float s[300];
    const float* base = g_sump + ((size_t)(isD*BB) + b)*4*300;
    for (int i = o; i < 300; i += 128)
        s[i] = base[i] + base[300+i] + base[600+i] + base[900+i];
    __syncthreads();
    float acc = 0.f;
    const float* w = bow_W + o*300;
    #pragma unroll 4
    for (int k = 0; k < 300; k++) acc = fmaf(s[k], w[k], acc);
    int L = isD ? LDV : LQV;
    g_bow[(isD*BB + b)*128 + o] = acc + (float)L * bow_b[o];
}

// ---------------- warp-MMA gathered GEMM (bf16 3-term split, fp32 accum) ----
// 256 threads, block tile 128x128, warp tile 32x64 (warp grid 4m x 2n).
// A = gathered emb rows hi/lo bf16 in smem [m][k]; B = pre-split weights [n][k].
// D += Ah*Bh + Al*Bh + Ah*Bl.
__global__ void __launch_bounds__(256) k_gemm_mma(const int* qwt, const int* dwt,
                                                  const int* qet, const int* det,
                                                  const float* emb) {
    extern __shared__ char dsm[];
    int t = threadIdx.x;
    int warp = t >> 5, lane = t & 31;
    int wm = warp >> 1, wn = warp & 1;        // 4 x 2 warp grid
    int g = lane >> 2, tq = lane & 3;

    int blk = blockIdx.x;
    const int* tokens; float* Y; int ldY, sl, mb, swi;
    if (blk < TB_QW) {
        sl = blk / 10; mb = blk % 10; tokens = qwt; Y = g_Yq; ldY = 768; swi = sl;
    } else if (blk < TB_QW + TB_DW) {
        int r = blk - TB_QW; sl = r / 256; mb = r % 256; tokens = dwt; Y = g_Yd; ldY = 768; swi = sl;
    } else if (blk < TB_QW + TB_DW + TB_QD) {
        int r = blk - (TB_QW + TB_DW); sl = r / 50; mb = r % 50;
        tokens = qet; Y = g_Ydesc; ldY = 640; swi = 6 + sl;
    } else {
        int r = blk - (TB_QW + TB_DW + TB_QD); sl = r / 100; mb = r % 100;
        tokens = det; Y = g_Ydesc + (size_t)6400*640; ldY = 640; swi = 6 + sl;
    }
    int m0 = mb * 128;

    int* toksm = (int*)(dsm + OFF_TOKS);
    if (t < 128) toksm[t] = tokens[m0 + t];
    __syncthreads();

    const __nv_bfloat16* wH = g_WbH + (size_t)swi*128*KPAD;
    const __nv_bfloat16* wL = g_WbL + (size_t)swi*128*KPAD;

    float c[2][8][4];
    #pragma unroll
    for (int mt = 0; mt < 2; mt++)
        #pragma unroll
        for (int nt = 0; nt < 8; nt++)
            #pragma unroll
            for (int i = 0; i < 4; i++) c[mt][nt][i] = 0.f;

    for (int ch = 0; ch < NCHUNK; ch++) {
        int k0 = ch * 64;
        if (ch) __syncthreads();               // frag reads done before restage
        // stage A (gather + hi/lo split): 128 rows x 64 k
        for (int e = t; e < 2048; e += 256) {
            int r = e >> 4, col = (e & 15) * 4;
            float4 v = make_float4(0.f, 0.f, 0.f, 0.f);
            if (k0 + col + 4 <= 300)
                v = *(const float4*)(emb + (size_t)toksm[r]*300 + k0 + col);
            __nv_bfloat16 h0 = __float2bfloat16(v.x), h1 = __float2bfloat16(v.y);
            __nv_bfloat16 h2 = __float2bfloat16(v.z), h3 = __float2bfloat16(v.w);
            __nv_bfloat16 l0 = __float2bfloat16(v.x - __bfloat162float(h0));
            __nv_bfloat16 l1 = __float2bfloat16(v.y - __bfloat162float(h1));
            __nv_bfloat16 l2 = __float2bfloat16(v.z - __bfloat162float(h2));
            __nv_bfloat16 l3 = __float2bfloat16(v.w - __bfloat162float(h3));
            int off = r*APITCH + col*2;
            uint2 hp, lp;
            hp.x = ((uint32_t)__bfloat16_as_ushort(h1) << 16) | __bfloat16_as_ushort(h0);
            hp.y = ((uint32_t)__bfloat16_as_ushort(h3) << 16) | __bfloat16_as_ushort(h2);
            lp.x = ((uint32_t)__bfloat16_as_ushort(l1) << 16) | __bfloat16_as_ushort(l0);
            lp.y = ((uint32_t)__bfloat16_as_ushort(l3) << 16) | __bfloat16_as_ushort(l2);
            *(uint2*)(dsm + OFF_AHI + off) = hp;
            *(uint2*)(dsm + OFF_ALO + off) = lp;
        }
        // stage B: 128 n-rows x 64 k, hi + lo (16 B chunks; KPAD pre-zeroed)
        for (int e = t; e < 2048; e += 256) {
            int buf = e >> 10, r = (e >> 3) & 127, gg = e & 7;
            const __nv_bfloat16* src = (buf ? wL : wH) + (size_t)r*KPAD + k0 + gg*8;
            int off = r*APITCH + gg*16;
            char* dst = dsm + (buf ? OFF_BLO : OFF_BHI) + off;
            *(uint4*)dst = *(const uint4*)src;
        }
        __syncthreads();

        #pragma unroll
        for (int ks = 0; ks < 4; ks++) {
            int kb = ks * 32;                  // 16 bf16 = 32 bytes
            uint32_t ah[2][4], al[2][4];
            #pragma unroll
            for (int mt = 0; mt < 2; mt++) {
                int row = wm*32 + mt*16 + g;
                int b0 = row*APITCH + kb + tq*4;
                int b1 = (row+8)*APITCH + kb + tq*4;
                ah[mt][0] = *(const uint32_t*)(dsm + OFF_AHI + b0);
                ah[mt][1] = *(const uint32_t*)(dsm + OFF_AHI + b1);
                ah[mt][2] = *(const uint32_t*)(dsm + OFF_AHI + b0 + 16);
                ah[mt][3] = *(const uint32_t*)(dsm + OFF_AHI + b1 + 16);
                al[mt][0] = *(const uint32_t*)(dsm + OFF_ALO + b0);
                al[mt][1] = *(const uint32_t*)(dsm + OFF_ALO + b1);
                al[mt][2] = *(const uint32_t*)(dsm + OFF_ALO + b0 + 16);
                al[mt][3] = *(const uint32_t*)(dsm + OFF_ALO + b1 + 16);
            }
            #pragma unroll
            for (int nt = 0; nt < 8; nt++) {
                int coln = wn*64 + nt*8 + g;
                int bb = coln*APITCH + kb + tq*4;
                uint32_t bh0 = *(const uint32_t*)(dsm + OFF_BHI + bb);
                uint32_t bh1 = *(const uint32_t*)(dsm + OFF_BHI + bb + 16);
                uint32_t bl0 = *(const uint32_t*)(dsm + OFF_BLO + bb);
                uint32_t bl1 = *(const uint32_t*)(dsm + OFF_BLO + bb + 16);
                #pragma unroll
                for (int mt = 0; mt < 2; mt++) {
                    mma_bf16(c[mt][nt], ah[mt], bh0, bh1);
                    mma_bf16(c[mt][nt], al[mt], bh0, bh1);
                    mma_bf16(c[mt][nt], ah[mt], bl0, bl1);
                }
            }
        }
    }

    // epilogue: c-frag layout c0=(g,2tq) c1=(g,2tq+1) c2=(g+8,2tq) c3=(g+8,2tq+1)
    #pragma unroll
    for (int mt = 0; mt < 2; mt++) {
        int row = m0 + wm*32 + mt*16 + g;
        #pragma unroll
        for (int nt = 0; nt < 8; nt++) {
            int col = sl*128 + wn*64 + nt*8 + 2*tq;
            float2 v0 = make_float2(c[mt][nt][0], c[mt][nt][1]);
            float2 v1 = make_float2(c[mt][nt][2], c[mt][nt][3]);
            *(float2*)&Y[(size_t)row*ldY + col] = v0;
            *(float2*)&Y[(size_t)(row+8)*ldY + col] = v1;
        }
    }
}

// ---------------- combine conv slices + relu + l2 normalize ----------------
template<int ISD>
__global__ void k_combine(const float* ub, const float* bbias, const float* tb) {
    const float* Y = ISD ? g_Yd : g_Yq;
    float* outU = ISD ? g_du : g_qu;
    float* outB = ISD ? g_db : g_qb;
    float* outT = ISD ? g_dt : g_qt;
    const int L = ISD ? LDV : LQV;

    int idx = blockIdx.x;
    int l = idx % L;
    int o = threadIdx.x;
    const float* y0 = Y + (size_t)idx * 768;
    float u = fmaxf(y0[o] + ub[o], 0.f);
    bool hasB = (l < L-1), hasT = (l < L-2);
    float bv = 0.f, tv = 0.f;
    if (hasB) bv = fmaxf(y0[128+o] + y0[768+256+o] + bbias[o], 0.f);
    if (hasT) tv = fmaxf(y0[384+o] + y0[768+512+o] + y0[1536+640+o] + tb[o], 0.f);
    float su = block_sum_128(u*u);
    float sb = block_sum_128(bv*bv);
    float st = block_sum_128(tv*tv);
    int b = idx / L;
    outU[(size_t)idx*128 + o] = u / fmaxf(sqrtf(su), 1e-10f);
    if (hasB) outB[((size_t)b*(L-1) + l)*128 + o] = bv / fmaxf(sqrtf(sb), 1e-10f);
    if (hasT) outT[((size_t)b*(L-2) + l)*128 + o] = tv / fmaxf(sqrtf(st), 1e-10f);
}

// ---------------- entity branch ----------------
__global__ void k_ent(const int* qei, const int* qew, const int* dei, const int* dew,
                      const float* ent_emb, const float* car_emb, const float* des_b) {
    int x = blockIdx.x;
    bool isQ = x < BB*EQV;
    int o = threadIdx.x;
    int b, e, rowbase, eid;
    const int* carIds; const float* bow;
    if (isQ) {
        b = x / EQV; e = x % EQV;
        rowbase = x * DESCV;
        carIds = qew + b*EQV*KCV + e*KCV;
        eid = qei[b*EQV + e];
        bow = g_bow + (size_t)b*128;
    } else {
        int xi = x - BB*EQV;
        b = xi / EDV; e = xi % EDV;
        rowbase = BB*EQV*DESCV + xi*DESCV;
        carIds = dew + b*EDV*KCV + e*KCV;
        eid = dei[b*EDV + e];
        bow = g_bow + (size_t)(BB + b)*128;
    }
    float bias = des_b[o];
    float mx = 0.f;
    for (int pos = 0; pos < 16; pos++) {
        float sacc = bias;
        #pragma unroll
        for (int i = 0; i < 5; i++)
            sacc += g_Ydesc[(size_t)(rowbase + pos + i)*640 + i*128 + o];
        mx = fmaxf(mx, sacc);
    }
    __shared__ float bs[128];
    __shared__ float tS[10][128];
    __shared__ float sc[10];
    __shared__ float att[10];
    bs[o] = bow[o];
    __syncthreads();
    for (int k = 0; k < 10; k++) {
        float v = car_emb[(size_t)carIds[k]*128 + o];
        tS[k][o] = v;
        float p = block_sum_128(bs[o] * v);
        if (o == 0) sc[k] = p;
    }
    __syncthreads();
    if (o == 0) {
        float m = sc[0];
        #pragma unroll
        for (int k = 1; k < 10; k++) m = fmaxf(m, sc[k]);
        float sum = 0.f;
        #pragma unroll
        for (int k = 0; k < 10; k++) { att[k] = expf(sc[k] - m); sum += att[k]; }
        float inv = 1.f / sum;
        #pragma unroll
        for (int k = 0; k < 10; k++) att[k] *= inv;
    }
    __syncthreads();
    float ew = 0.f;
    #pragma unroll
    for (int k = 0; k < 10; k++) ew = fmaf(att[k], tS[k][o], ew);
    float val = ent_emb[(size_t)eid*128 + o] + mx + ew;
    float nsq = block_sum_128(val * val);
    float nv = val / fmaxf(sqrtf(nsq), 1e-10f);
    if (isQ) g_qs[(size_t)(b*EQV + e)*128 + o] = nv;
    else     g_ds[(size_t)(b*EDV + e)*128 + o] = nv;
}

// ---------------- kernel pooling ----------------
__global__ void __launch_bounds__(256) k_pool(const float* qwm, const float* qem,
                                              const float* dwm, const float* dem) {
    int blk = blockIdx.x;
    int b = blk >> 4, p = blk & 15;
    int qt = c_poolQ[p], dt = c_poolD[p];

    const float* Q; int Lq; const float* mqp;
    switch (qt) {
        case 0: Q = g_qu + (size_t)b*20*128; Lq = 20; mqp = qwm + b*LQV; break;
        case 1: Q = g_qb + (size_t)b*19*128; Lq = 19; mqp = qwm + b*LQV; break;
        case 2: Q = g_qt + (size_t)b*18*128; Lq = 18; mqp = qwm + b*LQV; break;
        default:Q = g_qs + (size_t)b*5*128;  Lq = 5;  mqp = qem + b*EQV; break;
    }
    const float* Dp; int Ld; const float* mdp;
    switch (dt) {
        case 0: Dp = g_du + (size_t)b*512*128; Ld = 512; mdp = dwm + b*LDV; break;
        case 1: Dp = g_db + (size_t)b*511*128; Ld = 511; mdp = dwm + b*LDV; break;
        case 2: Dp = g_dt + (size_t)b*510*128; Ld = 510; mdp = dwm + b*LDV; break;
        default:Dp = g_ds + (size_t)b*10*128;  Ld = 10;  mdp = dem + b*EDV; break;
    }

    __shared__ float Qs[20][132];
    __shared__ float DtS[128][36];
    __shared__ float simS[20][36];
    __shared__ float mdS[32];
    __shared__ float lpsS[20*11];

    int t = threadIdx.x;
    for (int e = t; e < Lq*128; e += 256) { int q = e >> 7, k = e & 127; Qs[q][k] = Q[e]; }

    int myq = t / 11, myk = t % 11;
    bool active = t < Lq * 11;
    float mu_ = c_MU[myk], is2 = c_IS2[myk];
    float acc = 0.f;

    for (int cc0 = 0; cc0 < Ld; cc0 += 32) {
        int cn = min(32, Ld - cc0);
        __syncthreads();
        for (int e = t; e < cn*128; e += 256) {
            int cc = e >> 7, k = e & 127;
            DtS[k][cc] = Dp[(size_t)(cc0 + cc)*128 + k];
        }
        if (t < cn) mdS[t] = mdp[cc0 + t];
        __syncthreads();
        int ncg = (cn + 3) >> 2;
        for (int mt = t; mt < Lq*8; mt += 256) {
            int q = mt >> 3, cg = mt & 7;
            if (cg < ncg) {
                float s0 = 0.f, s1 = 0.f, s2 = 0.f, s3 = 0.f;
                const float* qrow = &Qs[q][0];
                #pragma unroll 4
                for (int kk = 0; kk < 128; kk++) {
                    float qa = qrow[kk];
                    float4 d4 = *(const float4*)&DtS[kk][cg << 2];
                    s0 = fmaf(qa, d4.x, s0);
                    s1 = fmaf(qa, d4.y, s1);
                    s2 = fmaf(qa, d4.z, s2);
                    s3 = fmaf(qa, d4.w, s3);
                }
                int cb = cg << 2;
                simS[q][cb] = s0; simS[q][cb+1] = s1; simS[q][cb+2] = s2; simS[q][cb+3] = s3;
            }
        }
        __syncthreads();
        if (active) {
            const float* srow = &simS[myq][0];
            for (int cc = 0; cc < cn; cc++) {
                float df = srow[cc] - mu_;
                acc = fmaf(mdS[cc], __expf(-df*df*is2), acc);
            }
        }
    }
    __syncthreads();
    if (active)
        lpsS[myq*11 + myk] = logf(fmaxf(acc, 1e-10f)) * 0.01f * mqp[myq];
    __syncthreads();
    if (t < 11) {
        float s = 0.f;
        for (int q = 0; q < Lq; q++) s += lpsS[q*11 + t];
        g_feats[b*176 + p*11 + t] = s;
    }
}

// ---------------- final dense + tanh ----------------
__global__ void k_final(const float* W, const float* b0, float* out) {
    int b = threadIdx.x;
    if (b < BB) {
        float s = b0[0];
        #pragma unroll 4
        for (int j = 0; j < 176; j++) s = fmaf(g_feats[b*176 + j], W[j], s);
        out[b] = tanhf(s);
    }
}

// ---------------- launch ----------------
extern "C" void kernel_launch(void* const* d_in, const int* in_sizes, int n_in,
                              void* d_out, int out_size) {
    const int*   qwt  = (const int*)  d_in[0];
    const float* qwm  = (const float*)d_in[1];
    const int*   qei  = (const int*)  d_in[2];
    const int*   qet  = (const int*)  d_in[3];
    const int*   qew  = (const int*)  d_in[4];
    const float* qem  = (const float*)d_in[5];
    const int*   dwt  = (const int*)  d_in[6];
    const float* dwm  = (const float*)d_in[7];
    const int*   dei  = (const int*)  d_in[8];
    const int*   det  = (const int*)  d_in[9];
    const int*   dew  = (const int*)  d_in[10];
    const float* dem  = (const float*)d_in[11];
    const float* wrd  = (const float*)d_in[12];
    const float* ente = (const float*)d_in[13];
    const float* care = (const float*)d_in[14];
    const float* bowW = (const float*)d_in[15];
    const float* bowb = (const float*)d_in[16];
    const float* uW   = (const float*)d_in[17];
    const float* ub   = (const float*)d_in[18];
    const float* bW   = (const float*)d_in[19];
    const float* bb   = (const float*)d_in[20];
    const float* tW   = (const float*)d_in[21];
    const float* tb   = (const float*)d_in[22];
    const float* dW   = (const float*)d_in[23];
    const float* db_  = (const float*)d_in[24];
    const float* fW   = (const float*)d_in[25];
    const float* fb   = (const float*)d_in[26];
    float* out = (float*)d_out;

    cudaFuncSetAttribute(k_gemm_mma, cudaFuncAttributeMaxDynamicSharedMemorySize, SMEM_DYN);

    k_prep_weights<<<240, 256>>>(uW, bW, tW, dW);
    k_sum_part<<<dim3(BB, 2, 4), 320>>>(qwt, dwt, wrd);
    k_bow<<<dim3(BB, 2), 128>>>(bowW, bowb);

    k_gemm_mma<<<TB_ALL, 256, SMEM_DYN>>>(qwt, dwt, qet, det, wrd);

    k_combine<0><<<BB*LQV, 128>>>(ub, bb, tb);
    k_combine<1><<<BB*LDV, 128>>>(ub, bb, tb);

    k_ent<<<BB*(EQV + EDV), 128>>>(qei, qew, dei, dew, ente, care, db_);
    k_pool<<<BB*16, 256>>>(qwm, qem, dwm, dem);
    k_final<<<1, 64>>>(fW, fb, out);
}

// round 15
// speedup vs baseline: 1.5870x; 1.0754x over previous
#include <cuda_runtime.h>
#include <cuda_bf16.h>
#include <stdint.h>
#include <math.h>

#define BB   64
#define LQV  20
#define LDV  512
#define DV   300
#define EQV  5
#define EDV  10
#define DESCV 20
#define KCV  10

// ---------------- GEMM geometry ----------------
#define KPAD      320              // 5 chunks x 64 bf16
#define NCHUNK    5
#define NSLICES   11               // 6 word + 5 desc
#define TB_QW 60                   // 10 tiles x 6 slices
#define TB_DW 1536                 // 256 x 6
#define TB_QD 250                  // 50 x 5
#define TB_DD 500                  // 100 x 5
#define TB_ALL (TB_QW + TB_DW + TB_QD + TB_DD)   // 2346

// dynamic smem layout (bytes). Tiles 128 rows x 64 k bf16, row pitch 72
// bf16 = 144 B (conflict-free frag loads: bank = (36r + t') mod 32 = lane).
#define APITCH    144
#define OFF_TOKS  0                // 128 ints
#define OFF_AHI   512
#define OFF_BHI   (OFF_AHI + 128*APITCH)   // 18944
#define OFF_BLO   (OFF_BHI + 128*APITCH)   // 37376
#define SMEM_DYN  (OFF_BLO + 128*APITCH)   // 55808

// ---------------- constants ----------------
__constant__ float c_MU[11]  = {1.0f,0.9f,0.7f,0.5f,0.3f,0.1f,-0.1f,-0.3f,-0.5f,-0.7f,-0.9f};
__constant__ float c_IS2[11] = {500000.0f,50.f,50.f,50.f,50.f,50.f,50.f,50.f,50.f,50.f,50.f};
__constant__ int c_poolQ[16] = {0,0,0,1,2,1,1,2,2,3,3,3,0,1,2,3};
__constant__ int c_poolD[16] = {0,2,1,0,0,1,2,1,2,0,1,2,3,3,3,3};

// ---------------- scratch ----------------
__device__ __nv_bfloat16 g_WbH[NSLICES*128*KPAD];   // weights bf16 hi [slice][n][k]
__device__ __nv_bfloat16 g_WbL[NSLICES*128*KPAD];   // weights bf16 lo
__device__ float g_Yq[BB*LQV*768];
__device__ float g_Yd[(size_t)BB*LDV*768];
__device__ float g_Ydesc[(size_t)19200*640];
__device__ float g_qu[BB*20*128];
__device__ float g_qb[BB*19*128];
__device__ float g_qt[BB*18*128];
__device__ float g_du[(size_t)BB*512*128];
__device__ float g_db[(size_t)BB*511*128];
__device__ float g_dt[(size_t)BB*510*128];
__device__ float g_qs[BB*5*128];
__device__ float g_ds[BB*10*128];
__device__ float g_sump[2*BB*4*300];
__device__ float g_bow[2*BB*128];
__device__ float g_feats[BB*176];

// ---------------- helpers ----------------
__device__ __forceinline__ void mma_bf16(float* c, const uint32_t* a,
                                         uint32_t b0, uint32_t b1) {
    asm volatile("mma.sync.aligned.m16n8k16.row.col.f32.bf16.bf16.f32 "
        "{%0,%1,%2,%3}, {%4,%5,%6,%7}, {%8,%9}, {%0,%1,%2,%3};"
        : "+f"(c[0]), "+f"(c[1]), "+f"(c[2]), "+f"(c[3])
        : "r"(a[0]), "r"(a[1]), "r"(a[2]), "r"(a[3]), "r"(b0), "r"(b1));
}

__device__ __forceinline__ float warp_allreduce(float v) {
    v += __shfl_xor_sync(0xffffffffu, v, 16);
    v += __shfl_xor_sync(0xffffffffu, v, 8);
    v += __shfl_xor_sync(0xffffffffu, v, 4);
    v += __shfl_xor_sync(0xffffffffu, v, 2);
    v += __shfl_xor_sync(0xffffffffu, v, 1);
    return v;
}

__device__ __forceinline__ float block_sum_128(float v) {
    __shared__ float sh[4];
    v += __shfl_down_sync(0xffffffffu, v, 16);
    v += __shfl_down_sync(0xffffffffu, v, 8);
    v += __shfl_down_sync(0xffffffffu, v, 4);
    v += __shfl_down_sync(0xffffffffu, v, 2);
    v += __shfl_down_sync(0xffffffffu, v, 1);
    if ((threadIdx.x & 31) == 0) sh[threadIdx.x >> 5] = v;
    __syncthreads();
    float r = sh[0] + sh[1] + sh[2] + sh[3];
    __syncthreads();
    return r;
}

// ---------------- weight prep: fp32 -> bf16 hi/lo, [slice][n][kpad] ----------
__global__ void k_prep_weights(const float* uW, const float* bW, const float* tW, const float* dW) {
    int stride = gridDim.x * blockDim.x;
    for (int e = blockIdx.x*blockDim.x + threadIdx.x; e < NSLICES*128*KPAD; e += stride) {
        int s = e / (128*KPAD); int r = e % (128*KPAD); int n = r / KPAD; int k = r % KPAD;
        float v = 0.f;
        if (k < 300) {
            if (s == 0)      v = uW[n*300 + k];
            else if (s <= 2) v = bW[n*600 + (s-1)*300 + k];
            else if (s <= 5) v = tW[n*900 + (s-3)*300 + k];
            else             v = dW[n*1500 + (s-6)*300 + k];
        }
        __nv_bfloat16 h = __float2bfloat16(v);
        __nv_bfloat16 l = __float2bfloat16(v - __bfloat162float(h));
        g_WbH[e] = h; g_WbL[e] = l;
    }
}

// ---------------- partial embedding sums (for bow) ----------------
__global__ void k_sum_part(const int* qwt, const int* dwt, const float* emb) {
    int dim = threadIdx.x; if (dim >= 300) return;
    int b = blockIdx.x; int isD = blockIdx.y; int sl = blockIdx.z;
    const int* tok; int L;
    if (isD) { tok = dwt + b*LDV; L = LDV; } else { tok = qwt + b*LQV; L = LQV; }
    int per = (L + 3) >> 2;
    int l0 = sl * per; int l1 = min(L, l0 + per);
    float s0 = 0.f, s1 = 0.f, s2 = 0.f, s3 = 0.f;
    int l = l0;
    for (; l + 4 <= l1; l += 4) {
        s0 += emb[(size_t)tok[l  ]*300 + dim];
        s1 += emb[(size_t)tok[l+1]*300 + dim];
        s2 += emb[(size_t)tok[l+2]*300 + dim];
        s3 += emb[(size_t)tok[l+3]*300 + dim];
    }
    for (; l < l1; l++) s0 += emb[(size_t)tok[l]*300 + dim];
    g_sump[(((isD*BB) + b)*4 + sl)*300 + dim] = s0 + s1 + s2 + s3;
}

// ---------------- bow projection ----------------
__global__ void k_bow(const float* bow_W, const float* bow_b) {
    int b = blockIdx.x, isD = blockIdx.y, o = threadIdx.x;
    __shared__ float s[300];
    const float* base = g_sump + ((size_t)(isD*BB) + b)*4*300;
    for (int i = o; i < 300; i += 128)
        s[i] = base[i] + base[300+i] + base[600+i] + base[900+i];
    __syncthreads();
    float acc = 0.f;
    const float* w = bow_W + o*300;
    #pragma unroll 4
    for (int k = 0; k < 300; k++) acc = fmaf(s[k], w[k], acc);
    int L = isD ? LDV : LQV;
    g_bow[(isD*BB + b)*128 + o] = acc + (float)L * bow_b[o];
}

// ---------------- warp-MMA gathered GEMM (2-term split, fp32 accum) ---------
// 256 threads, block tile 128x128, warp tile 32x64 (warp grid 4m x 2n).
// A = gathered emb rows bf16(hi) in smem [m][k]; B = pre-split weights [n][k].
// D += Ah*Bh + Ah*Bl  (= Ah*B; error limited to A quantization ~2^-9).
__global__ void __launch_bounds__(256) k_gemm_mma(const int* qwt, const int* dwt,
                                                  const int* qet, const int* det,
                                                  const float* emb) {
    extern __shared__ char dsm[];
    int t = threadIdx.x;
    int warp = t >> 5, lane = t & 31;
    int wm = warp >> 1, wn = warp & 1;        // 4 x 2 warp grid
    int g = lane >> 2, tq = lane & 3;

    int blk = blockIdx.x;
    const int* tokens; float* Y; int ldY, sl, mb, swi;
    if (blk < TB_QW) {
        sl = blk / 10; mb = blk % 10; tokens = qwt; Y = g_Yq; ldY = 768; swi = sl;
    } else if (blk < TB_QW + TB_DW) {
        int r = blk - TB_QW; sl = r / 256; mb = r % 256; tokens = dwt; Y = g_Yd; ldY = 768; swi = sl;
    } else if (blk < TB_QW + TB_DW + TB_QD) {
        int r = blk - (TB_QW + TB_DW); sl = r / 50; mb = r % 50;
        tokens = qet; Y = g_Ydesc; ldY = 640; swi = 6 + sl;
    } else {
        int r = blk - (TB_QW + TB_DW + TB_QD); sl = r / 100; mb = r % 100;
        tokens = det; Y = g_Ydesc + (size_t)6400*640; ldY = 640; swi = 6 + sl;
    }
    int m0 = mb * 128;

    int* toksm = (int*)(dsm + OFF_TOKS);
    if (t < 128) toksm[t] = tokens[m0 + t];
    __syncthreads();

    const __nv_bfloat16* wH = g_WbH + (size_t)swi*128*KPAD;
    const __nv_bfloat16* wL = g_WbL + (size_t)swi*128*KPAD;

    float c[2][8][4];
    #pragma unroll
    for (int mt = 0; mt < 2; mt++)
        #pragma unroll
        for (int nt = 0; nt < 8; nt++)
            #pragma unroll
            for (int i = 0; i < 4; i++) c[mt][nt][i] = 0.f;

    for (int ch = 0; ch < NCHUNK; ch++) {
        int k0 = ch * 64;
        if (ch) __syncthreads();               // frag reads done before restage
        // stage A (gather, bf16 hi only): 128 rows x 64 k
        for (int e = t; e < 2048; e += 256) {
            int r = e >> 4, col = (e & 15) * 4;
            float4 v = make_float4(0.f, 0.f, 0.f, 0.f);
            if (k0 + col + 4 <= 300)
                v = *(const float4*)(emb + (size_t)toksm[r]*300 + k0 + col);
            __nv_bfloat16 h0 = __float2bfloat16(v.x), h1 = __float2bfloat16(v.y);
            __nv_bfloat16 h2 = __float2bfloat16(v.z), h3 = __float2bfloat16(v.w);
            uint2 hp;
            hp.x = ((uint32_t)__bfloat16_as_ushort(h1) << 16) | __bfloat16_as_ushort(h0);
            hp.y = ((uint32_t)__bfloat16_as_ushort(h3) << 16) | __bfloat16_as_ushort(h2);
            *(uint2*)(dsm + OFF_AHI + r*APITCH + col*2) = hp;
        }
        // stage B: 128 n-rows x 64 k, hi + lo (16 B chunks; KPAD pre-zeroed)
        for (int e = t; e < 2048; e += 256) {
            int buf = e >> 10, r = (e >> 3) & 127, gg = e & 7;
            const __nv_bfloat16* src = (buf ? wL : wH) + (size_t)r*KPAD + k0 + gg*8;
            int off = r*APITCH + gg*16;
            char* dst = dsm + (buf ? OFF_BLO : OFF_BHI) + off;
            *(uint4*)dst = *(const uint4*)src;
        }
        __syncthreads();

        #pragma unroll
        for (int ks = 0; ks < 4; ks++) {
            int kb = ks * 32;                  // 16 bf16 = 32 bytes
            uint32_t ah[2][4];
            #pragma unroll
            for (int mt = 0; mt < 2; mt++) {
                int row = wm*32 + mt*16 + g;
                int b0 = row*APITCH + kb + tq*4;
                int b1 = (row+8)*APITCH + kb + tq*4;
                ah[mt][0] = *(const uint32_t*)(dsm + OFF_AHI + b0);
                ah[mt][1] = *(const uint32_t*)(dsm + OFF_AHI + b1);
                ah[mt][2] = *(const uint32_t*)(dsm + OFF_AHI + b0 + 16);
                ah[mt][3] = *(const uint32_t*)(dsm + OFF_AHI + b1 + 16);
            }
            #pragma unroll
            for (int nt = 0; nt < 8; nt++) {
                int coln = wn*64 + nt*8 + g;
                int bb = coln*APITCH + kb + tq*4;
                uint32_t bh0 = *(const uint32_t*)(dsm + OFF_BHI + bb);
                uint32_t bh1 = *(const uint32_t*)(dsm + OFF_BHI + bb + 16);
                uint32_t bl0 = *(const uint32_t*)(dsm + OFF_BLO + bb);
                uint32_t bl1 = *(const uint32_t*)(dsm + OFF_BLO + bb + 16);
                #pragma unroll
                for (int mt = 0; mt < 2; mt++) {
                    mma_bf16(c[mt][nt], ah[mt], bh0, bh1);
                    mma_bf16(c[mt][nt], ah[mt], bl0, bl1);
                }
            }
        }
    }

    // epilogue: c-frag layout c0=(g,2tq) c1=(g,2tq+1) c2=(g+8,2tq) c3=(g+8,2tq+1)
    #pragma unroll
    for (int mt = 0; mt < 2; mt++) {
        int row = m0 + wm*32 + mt*16 + g;
        #pragma unroll
        for (int nt = 0; nt < 8; nt++) {
            int col = sl*128 + wn*64 + nt*8 + 2*tq;
            float2 v0 = make_float2(c[mt][nt][0], c[mt][nt][1]);
            float2 v1 = make_float2(c[mt][nt][2], c[mt][nt][3]);
            *(float2*)&Y[(size_t)row*ldY + col] = v0;
            *(float2*)&Y[(size_t)(row+8)*ldY + col] = v1;
        }
    }
}

// ---------------- combine conv slices + relu + l2 normalize ----------------
// One warp per sequence position; 4 positions per 128-thread block. No barriers.
template<int ISD>
__global__ void k_combine(const float* ub, const float* bbias, const float* tb) {
    const float* Y = ISD ? g_Yd : g_Yq;
    float* outU = ISD ? g_du : g_qu;
    float* outB = ISD ? g_db : g_qb;
    float* outT = ISD ? g_dt : g_qt;
    const int L = ISD ? LDV : LQV;

    int idx = blockIdx.x * 4 + (threadIdx.x >> 5);
    int lane = threadIdx.x & 31;
    int l = idx % L;
    int b = idx / L;
    const float* y0 = Y + (size_t)idx * 768;
    bool hasB = (l < L-1), hasT = (l < L-2);

    float u[4], bv[4], tv[4];
    float su = 0.f, sb = 0.f, st = 0.f;
    #pragma unroll
    for (int j = 0; j < 4; j++) {
        int o = lane + 32*j;
        u[j] = fmaxf(y0[o] + ub[o], 0.f);
        su = fmaf(u[j], u[j], su);
        bv[j] = 0.f; tv[j] = 0.f;
        if (hasB) {
            bv[j] = fmaxf(y0[128+o] + y0[768+256+o] + bbias[o], 0.f);
            sb = fmaf(bv[j], bv[j], sb);
        }
        if (hasT) {
            tv[j] = fmaxf(y0[384+o] + y0[768+512+o] + y0[1536+640+o] + tb[o], 0.f);
            st = fmaf(tv[j], tv[j], st);
        }
    }
    su = warp_allreduce(su);
    sb = warp_allreduce(sb);
    st = warp_allreduce(st);
    float iu = 1.f / fmaxf(sqrtf(su), 1e-10f);
    float ib = 1.f / fmaxf(sqrtf(sb), 1e-10f);
    float it = 1.f / fmaxf(sqrtf(st), 1e-10f);
    #pragma unroll
    for (int j = 0; j < 4; j++) {
        int o = lane + 32*j;
        outU[(size_t)idx*128 + o] = u[j] * iu;
        if (hasB) outB[((size_t)b*(L-1) + l)*128 + o] = bv[j] * ib;
        if (hasT) outT[((size_t)b*(L-2) + l)*128 + o] = tv[j] * it;
    }
}

// ---------------- entity branch ----------------
__global__ void k_ent(const int* qei, const int* qew, const int* dei, const int* dew,
                      const float* ent_emb, const float* car_emb, const float* des_b) {
    int x = blockIdx.x;
    bool isQ = x < BB*EQV;
    int o = threadIdx.x;
    int b, e, rowbase, eid;
    const int* carIds; const float* bow;
    if (isQ) {
        b = x / EQV; e = x % EQV;
        rowbase = x * DESCV;
        carIds = qew + b*EQV*KCV + e*KCV;
        eid = qei[b*EQV + e];
        bow = g_bow + (size_t)b*128;
    } else {
        int xi = x - BB*EQV;
        b = xi / EDV; e = xi % EDV;
        rowbase = BB*EQV*DESCV + xi*DESCV;
        carIds = dew + b*EDV*KCV + e*KCV;
        eid = dei[b*EDV + e];
        bow = g_bow + (size_t)(BB + b)*128;
    }
    float bias = des_b[o];
    float mx = 0.f;
    for (int pos = 0; pos < 16; pos++) {
        float sacc = bias;
        #pragma unroll
        for (int i = 0; i < 5; i++)
            sacc += g_Ydesc[(size_t)(rowbase + pos + i)*640 + i*128 + o];
        mx = fmaxf(mx, sacc);
    }
    __shared__ float bs[128];
    __shared__ float tS[10][128];
    __shared__ float sc[10];
    __shared__ float att[10];
    bs[o] = bow[o];
    __syncthreads();
    for (int k = 0; k < 10; k++) {
        float v = car_emb[(size_t)carIds[k]*128 + o];
        tS[k][o] = v;
        float p = block_sum_128(bs[o] * v);
        if (o == 0) sc[k] = p;
    }
    __syncthreads();
    if (o == 0) {
        float m = sc[0];
        #pragma unroll
        for (int k = 1; k < 10; k++) m = fmaxf(m, sc[k]);
        float sum = 0.f;
        #pragma unroll
        for (int k = 0; k < 10; k++) { att[k] = expf(sc[k] - m); sum += att[k]; }
        float inv = 1.f / sum;
        #pragma unroll
        for (int k = 0; k < 10; k++) att[k] *= inv;
    }
    __syncthreads();
    float ew = 0.f;
    #pragma unroll
    for (int k = 0; k < 10; k++) ew = fmaf(att[k], tS[k][o], ew);
    float val = ent_emb[(size_t)eid*128 + o] + mx + ew;
    float nsq = block_sum_128(val * val);
    float nv = val / fmaxf(sqrtf(nsq), 1e-10f);
    if (isQ) g_qs[(size_t)(b*EQV + e)*128 + o] = nv;
    else     g_ds[(size_t)(b*EDV + e)*128 + o] = nv;
}

// ---------------- kernel pooling ----------------
__global__ void __launch_bounds__(256) k_pool(const float* qwm, const float* qem,
                                              const float* dwm, const float* dem) {
    int blk = blockIdx.x;
    int b = blk >> 4, p = blk & 15;
    int qt = c_poolQ[p], dt = c_poolD[p];

    const float* Q; int Lq; const float* mqp;
    switch (qt) {
        case 0: Q = g_qu + (size_t)b*20*128; Lq = 20; mqp = qwm + b*LQV; break;
        case 1: Q = g_qb + (size_t)b*19*128; Lq = 19; mqp = qwm + b*LQV; break;
        case 2: Q = g_qt + (size_t)b*18*128; Lq = 18; mqp = qwm + b*LQV; break;
        default:Q = g_qs + (size_t)b*5*128;  Lq = 5;  mqp = qem + b*EQV; break;
    }
    const float* Dp; int Ld; const float* mdp;
    switch (dt) {
        case 0: Dp = g_du + (size_t)b*512*128; Ld = 512; mdp = dwm + b*LDV; break;
        case 1: Dp = g_db + (size_t)b*511*128; Ld = 511; mdp = dwm + b*LDV; break;
        case 2: Dp = g_dt + (size_t)b*510*128; Ld = 510; mdp = dwm + b*LDV; break;
        default:Dp = g_ds + (size_t)b*10*128;  Ld = 10;  mdp = dem + b*EDV; break;
    }

    __shared__ float Qs[20][132];
    __shared__ float DtS[128][36];
    __shared__ float simS[20][36];
    __shared__ float mdS[32];
    __shared__ float lpsS[20*11];

    int t = threadIdx.x;
    for (int e = t; e < Lq*128; e += 256) { int q = e >> 7, k = e & 127; Qs[q][k] = Q[e]; }

    int myq = t / 11, myk = t % 11;
    bool active = t < Lq * 11;
    float mu_ = c_MU[myk], is2 = c_IS2[myk];
    float acc = 0.f;

    for (int cc0 = 0; cc0 < Ld; cc0 += 32) {
        int cn = min(32, Ld - cc0);
        __syncthreads();
        for (int e = t; e < cn*128; e += 256) {
            int cc = e >> 7, k = e & 127;
            DtS[k][cc] = Dp[(size_t)(cc0 + cc)*128 + k];
        }
        if (t < cn) mdS[t] = mdp[cc0 + t];
        __syncthreads();
        int ncg = (cn + 3) >> 2;
        for (int mt = t; mt < Lq*8; mt += 256) {
            int q = mt >> 3, cg = mt & 7;
            if (cg < ncg) {
                float s0 = 0.f, s1 = 0.f, s2 = 0.f, s3 = 0.f;
                const float* qrow = &Qs[q][0];
                #pragma unroll 4
                for (int kk = 0; kk < 128; kk++) {
                    float qa = qrow[kk];
                    float4 d4 = *(const float4*)&DtS[kk][cg << 2];
                    s0 = fmaf(qa, d4.x, s0);
                    s1 = fmaf(qa, d4.y, s1);
                    s2 = fmaf(qa, d4.z, s2);
                    s3 = fmaf(qa, d4.w, s3);
                }
                int cb = cg << 2;
                simS[q][cb] = s0; simS[q][cb+1] = s1; simS[q][cb+2] = s2; simS[q][cb+3] = s3;
            }
        }
        __syncthreads();
        if (active) {
            const float* srow = &simS[myq][0];
            for (int cc = 0; cc < cn; cc++) {
                float df = srow[cc] - mu_;
                acc = fmaf(mdS[cc], __expf(-df*df*is2), acc);
            }
        }
    }
    __syncthreads();
    if (active)
        lpsS[myq*11 + myk] = logf(fmaxf(acc, 1e-10f)) * 0.01f * mqp[myq];
    __syncthreads();
    if (t < 11) {
        float s = 0.f;
        for (int q = 0; q < Lq; q++) s += lpsS[q*11 + t];
        g_feats[b*176 + p*11 + t] = s;
    }
}

// ---------------- final dense + tanh ----------------
__global__ void k_final(const float* W, const float* b0, float* out) {
    int b = threadIdx.x;
    if (b < BB) {
        float s = b0[0];
        #pragma unroll 4
        for (int j = 0; j < 176; j++) s = fmaf(g_feats[b*176 + j], W[j], s);
        out[b] = tanhf(s);
    }
}

// ---------------- launch ----------------
extern "C" void kernel_launch(void* const* d_in, const int* in_sizes, int n_in,
                              void* d_out, int out_size) {
    const int*   qwt  = (const int*)  d_in[0];
    const float* qwm  = (const float*)d_in[1];
    const int*   qei  = (const int*)  d_in[2];
    const int*   qet  = (const int*)  d_in[3];
    const int*   qew  = (const int*)  d_in[4];
    const float* qem  = (const float*)d_in[5];
    const int*   dwt  = (const int*)  d_in[6];
    const float* dwm  = (const float*)d_in[7];
    const int*   dei  = (const int*)  d_in[8];
    const int*   det  = (const int*)  d_in[9];
    const int*   dew  = (const int*)  d_in[10];
    const float* dem  = (const float*)d_in[11];
    const float* wrd  = (const float*)d_in[12];
    const float* ente = (const float*)d_in[13];
    const float* care = (const float*)d_in[14];
    const float* bowW = (const float*)d_in[15];
    const float* bowb = (const float*)d_in[16];
    const float* uW   = (const float*)d_in[17];
    const float* ub   = (const float*)d_in[18];
    const float* bW   = (const float*)d_in[19];
    const float* bb   = (const float*)d_in[20];
    const float* tW   = (const float*)d_in[21];
    const float* tb   = (const float*)d_in[22];
    const float* dW   = (const float*)d_in[23];
    const float* db_  = (const float*)d_in[24];
    const float* fW   = (const float*)d_in[25];
    const float* fb   = (const float*)d_in[26];
    float* out = (float*)d_out;

    cudaFuncSetAttribute(k_gemm_mma, cudaFuncAttributeMaxDynamicSharedMemorySize, SMEM_DYN);

    k_prep_weights<<<240, 256>>>(uW, bW, tW, dW);
    k_sum_part<<<dim3(BB, 2, 4), 320>>>(qwt, dwt, wrd);
    k_bow<<<dim3(BB, 2), 128>>>(bowW, bowb);

    k_gemm_mma<<<TB_ALL, 256, SMEM_DYN>>>(qwt, dwt, qet, det, wrd);

    k_combine<0><<<BB*LQV/4, 128>>>(ub, bb, tb);
    k_combine<1><<<BB*LDV/4, 128>>>(ub, bb, tb);

    k_ent<<<BB*(EQV + EDV), 128>>>(qei, qew, dei, dew, ente, care, db_);
    k_pool<<<BB*16, 256>>>(qwm, qem, dwm, dem);
    k_final<<<1, 64>>>(fW, fb, out);
}

// round 17
// speedup vs baseline: 2.0612x; 1.2988x over previous
#include <cuda_runtime.h>
#include <cuda_bf16.h>
#include <stdint.h>
#include <math.h>

#define BB   64
#define LQV  20
#define LDV  512
#define DV   300
#define EQV  5
#define EDV  10
#define DESCV 20
#define KCV  10
#define VW   50000

// ---------------- GEMM geometry ----------------
#define KPAD      320              // 5 chunks x 64 bf16
#define NCHUNK    5
#define NSLICES   11               // 6 word + 5 desc
#define TB_QW 60                   // 10 tiles x 6 slices
#define TB_DW 1536                 // 256 x 6
#define TB_QD 250                  // 50 x 5
#define TB_DD 500                  // 100 x 5
#define TB_ALL (TB_QW + TB_DW + TB_QD + TB_DD)   // 2346

// dynamic smem (bytes): toks + double-buffered A/B chunk tiles.
// Tile = 128 rows x 64 k bf16, row pitch 72 bf16 = 144 B (conflict-free frags).
#define APITCH    144
#define OFF_TOKS  0                // 128 ints
#define OFF_A0    512
#define OFF_B0    (OFF_A0 + 128*APITCH)    // 18944
#define OFF_A1    (OFF_B0 + 128*APITCH)    // 37376
#define OFF_B1    (OFF_A1 + 128*APITCH)    // 55808
#define SMEM_DYN  (OFF_B1 + 128*APITCH)    // 74240

// ---------------- constants ----------------
__constant__ float c_MU[11]  = {1.0f,0.9f,0.7f,0.5f,0.3f,0.1f,-0.1f,-0.3f,-0.5f,-0.7f,-0.9f};
__constant__ float c_IS2[11] = {500000.0f,50.f,50.f,50.f,50.f,50.f,50.f,50.f,50.f,50.f,50.f};
__constant__ int c_poolQ[16] = {0,0,0,1,2,1,1,2,2,3,3,3,0,1,2,3};
__constant__ int c_poolD[16] = {0,2,1,0,0,1,2,1,2,0,1,2,3,3,3,3};

// ---------------- scratch ----------------
__device__ __nv_bfloat16 g_WbH[NSLICES*128*KPAD];       // weights bf16 [slice][n][kpad]
__device__ __nv_bfloat16 g_EmbB[(size_t)VW*KPAD];       // bf16 embedding table, k-padded
__device__ float g_Yq[BB*LQV*768];
__device__ float g_Yd[(size_t)BB*LDV*768];
__device__ float g_Ydesc[(size_t)19200*640];
__device__ float g_qu[BB*20*128];
__device__ float g_qb[BB*19*128];
__device__ float g_qt[BB*18*128];
__device__ float g_du[(size_t)BB*512*128];
__device__ float g_db[(size_t)BB*511*128];
__device__ float g_dt[(size_t)BB*510*128];
__device__ float g_qs[BB*5*128];
__device__ float g_ds[BB*10*128];
__device__ float g_sump[2*BB*4*300];
__device__ float g_bow[2*BB*128];
__device__ float g_feats[BB*176];

// ---------------- helpers ----------------
__device__ __forceinline__ void mma_bf16(float* c, const uint32_t* a,
                                         uint32_t b0, uint32_t b1) {
    asm volatile("mma.sync.aligned.m16n8k16.row.col.f32.bf16.bf16.f32 "
        "{%0,%1,%2,%3}, {%4,%5,%6,%7}, {%8,%9}, {%0,%1,%2,%3};"
        : "+f"(c[0]), "+f"(c[1]), "+f"(c[2]), "+f"(c[3])
        : "r"(a[0]), "r"(a[1]), "r"(a[2]), "r"(a[3]), "r"(b0), "r"(b1));
}

__device__ __forceinline__ uint32_t smem_u32(const void* p) {
    uint32_t a;
    asm("{ .reg .u64 t; cvta.to.shared.u64 t, %1; cvt.u32.u64 %0, t; }" : "=r"(a) : "l"(p));
    return a;
}
__device__ __forceinline__ void cp16(uint32_t s, const void* g) {
    asm volatile("cp.async.cg.shared.global [%0], [%1], 16;" :: "r"(s), "l"(g) : "memory");
}
#define CP_COMMIT() asm volatile("cp.async.commit_group;" ::: "memory")
#define CP_WAIT1()  asm volatile("cp.async.wait_group 1;" ::: "memory")
#define CP_WAIT0()  asm volatile("cp.async.wait_group 0;" ::: "memory")

__device__ __forceinline__ float warp_allreduce(float v) {
    v += __shfl_xor_sync(0xffffffffu, v, 16);
    v += __shfl_xor_sync(0xffffffffu, v, 8);
    v += __shfl_xor_sync(0xffffffffu, v, 4);
    v += __shfl_xor_sync(0xffffffffu, v, 2);
    v += __shfl_xor_sync(0xffffffffu, v, 1);
    return v;
}

__device__ __forceinline__ float block_sum_128(float v) {
    __shared__ float sh[4];
    v += __shfl_down_sync(0xffffffffu, v, 16);
    v += __shfl_down_sync(0xffffffffu, v, 8);
    v += __shfl_down_sync(0xffffffffu, v, 4);
    v += __shfl_down_sync(0xffffffffu, v, 2);
    v += __shfl_down_sync(0xffffffffu, v, 1);
    if ((threadIdx.x & 31) == 0) sh[threadIdx.x >> 5] = v;
    __syncthreads();
    float r = sh[0] + sh[1] + sh[2] + sh[3];
    __syncthreads();
    return r;
}

// ---------------- weight prep: fp32 -> bf16 (rounded), [slice][n][kpad] -----
__global__ void k_prep_weights(const float* uW, const float* bW, const float* tW, const float* dW) {
    int stride = gridDim.x * blockDim.x;
    for (int e = blockIdx.x*blockDim.x + threadIdx.x; e < NSLICES*128*KPAD; e += stride) {
        int s = e / (128*KPAD); int r = e % (128*KPAD); int n = r / KPAD; int k = r % KPAD;
        float v = 0.f;
        if (k < 300) {
            if (s == 0)      v = uW[n*300 + k];
            else if (s <= 2) v = bW[n*600 + (s-1)*300 + k];
            else if (s <= 5) v = tW[n*900 + (s-3)*300 + k];
            else             v = dW[n*1500 + (s-6)*300 + k];
        }
        g_WbH[e] = __float2bfloat16(v);
    }
}

// ---------------- embedding prep: fp32 -> bf16, k-padded to 320 -------------
__global__ void k_prep_emb(const float* emb) {
    int stride = gridDim.x * blockDim.x;
    for (int e = blockIdx.x*blockDim.x + threadIdx.x; e < VW*80; e += stride) {
        int row = e / 80, c4 = e % 80;
        int col = c4 * 4;
        uint2 p = make_uint2(0u, 0u);
        if (col < 300) {
            float4 v = *(const float4*)(emb + (size_t)row*300 + col);
            __nv_bfloat16 h0 = __float2bfloat16(v.x), h1 = __float2bfloat16(v.y);
            __nv_bfloat16 h2 = __float2bfloat16(v.z), h3 = __float2bfloat16(v.w);
            p.x = ((uint32_t)__bfloat16_as_ushort(h1) << 16) | __bfloat16_as_ushort(h0);
            p.y = ((uint32_t)__bfloat16_as_ushort(h3) << 16) | __bfloat16_as_ushort(h2);
        }
        *(uint2*)(g_EmbB + (size_t)row*KPAD + col) = p;
    }
}

// ---------------- partial embedding sums (for bow) ----------------
__global__ void k_sum_part(const int* qwt, const int* dwt, const float* emb) {
    int dim = threadIdx.x; if (dim >= 300) return;
    int b = blockIdx.x; int isD = blockIdx.y; int sl = blockIdx.z;
    const int* tok; int L;
    if (isD) { tok = dwt + b*LDV; L = LDV; } else { tok = qwt + b*LQV; L = LQV; }
    int per = (L + 3) >> 2;
    int l0 = sl * per; int l1 = min(L, l0 + per);
    float s0 = 0.f, s1 = 0.f, s2 = 0.f, s3 = 0.f;
    int l = l0;
    for (; l + 4 <= l1; l += 4) {
        s0 += emb[(size_t)tok[l  ]*300 + dim];
        s1 += emb[(size_t)tok[l+1]*300 + dim];
        s2 += emb[(size_t)tok[l+2]*300 + dim];
        s3 += emb[(size_t)tok[l+3]*300 + dim];
    }
    for (; l < l1; l++) s0 += emb[(size_t)tok[l]*300 + dim];
    g_sump[(((isD*BB) + b)*4 + sl)*300 + dim] = s0 + s1 + s2 + s3;
}

// ---------------- bow projection ----------------
__global__ void k_bow(const float* bow_W, const float* bow_b) {
    int b = blockIdx.x, isD = blockIdx.y, o = threadIdx.x;
    __shared__ float s[300];
    const float* base = g_sump + ((size_t)(isD*BB) + b)*4*300;
    for (int i = o; i < 300; i += 128)
        s[i] = base[i] + base[300+i] + base[600+i] + base[900+i];
    __syncthreads();
    float acc = 0.f;
    const float* w = bow_W + o*300;
    #pragma unroll 4
    for (int k = 0; k < 300; k++) acc = fmaf(s[k], w[k], acc);
    int L = isD ? LDV : LQV;
    g_bow[(isD*BB + b)*128 + o] = acc + (float)L * bow_b[o];
}

// ---------------- warp-MMA gathered GEMM: cp.async double-buffered ----------
// 256 threads, block tile 128x128, warp tile 32x64 (4m x 2n warps).
// A = pre-converted bf16 emb rows (cp.async), B = pre-converted bf16 weights.
// Single-term D = Ah*Bh (both operands RN-rounded bf16; fp32 accumulate).
__global__ void __launch_bounds__(256) k_gemm_mma(const int* qwt, const int* dwt,
                                                  const int* qet, const int* det) {
    extern __shared__ char dsm[];
    int t = threadIdx.x;
    int warp = t >> 5, lane = t & 31;
    int wm = warp >> 1, wn = warp & 1;        // 4 x 2 warp grid
    int g = lane >> 2, tq = lane & 3;

    int blk = blockIdx.x;
    const int* tokens; float* Y; int ldY, sl, mb, swi;
    if (blk < TB_QW) {
        sl = blk / 10; mb = blk % 10; tokens = qwt; Y = g_Yq; ldY = 768; swi = sl;
    } else if (blk < TB_QW + TB_DW) {
        int r = blk - TB_QW; sl = r / 256; mb = r % 256; tokens = dwt; Y = g_Yd; ldY = 768; swi = sl;
    } else if (blk < TB_QW + TB_DW + TB_QD) {
        int r = blk - (TB_QW + TB_DW); sl = r / 50; mb = r % 50;
        tokens = qet; Y = g_Ydesc; ldY = 640; swi = 6 + sl;
    } else {
        int r = blk - (TB_QW + TB_DW + TB_QD); sl = r / 100; mb = r % 100;
        tokens = det; Y = g_Ydesc + (size_t)6400*640; ldY = 640; swi = 6 + sl;
    }
    int m0 = mb * 128;

    int* toksm = (int*)(dsm + OFF_TOKS);
    if (t < 128) toksm[t] = tokens[m0 + t];
    __syncthreads();

    const __nv_bfloat16* wH = g_WbH + (size_t)swi*128*KPAD;
    uint32_t sbase = smem_u32(dsm);
    const uint32_t offA[2] = {sbase + OFF_A0, sbase + OFF_A1};
    const uint32_t offB[2] = {sbase + OFF_B0, sbase + OFF_B1};
    const int offAc[2] = {OFF_A0, OFF_A1};
    const int offBc[2] = {OFF_B0, OFF_B1};

    float c[2][8][4];
    #pragma unroll
    for (int mt = 0; mt < 2; mt++)
        #pragma unroll
        for (int nt = 0; nt < 8; nt++)
            #pragma unroll
            for (int i = 0; i < 4; i++) c[mt][nt][i] = 0.f;

    // stage chunk 0 into buffer 0
    {
        int k0 = 0;
        #pragma unroll
        for (int e = t; e < 1024; e += 256) {
            int r = e >> 3, gg = e & 7;
            cp16(offA[0] + r*APITCH + gg*16, g_EmbB + (size_t)toksm[r]*KPAD + k0 + gg*8);
        }
        #pragma unroll
        for (int e = t; e < 1024; e += 256) {
            int r = e >> 3, gg = e & 7;
            cp16(offB[0] + r*APITCH + gg*16, wH + (size_t)r*KPAD + k0 + gg*8);
        }
        CP_COMMIT();
    }

    for (int ch = 0; ch < NCHUNK; ch++) {
        if (ch) __syncthreads();               // reads of the buffer we stage next are done
        if (ch < NCHUNK-1) {
            int k0 = (ch+1) * 64;
            int bf = (ch+1) & 1;
            #pragma unroll
            for (int e = t; e < 1024; e += 256) {
                int r = e >> 3, gg = e & 7;
                cp16(offA[bf] + r*APITCH + gg*16, g_EmbB + (size_t)toksm[r]*KPAD + k0 + gg*8);
            }
            #pragma unroll
            for (int e = t; e < 1024; e += 256) {
                int r = e >> 3, gg = e & 7;
                cp16(offB[bf] + r*APITCH + gg*16, wH + (size_t)r*KPAD + k0 + gg*8);
            }
            CP_COMMIT();
            CP_WAIT1();
        } else {
            CP_WAIT0();
        }
        __syncthreads();

        const char* Ab = dsm + offAc[ch & 1];
        const char* Bb = dsm + offBc[ch & 1];
        #pragma unroll
        for (int ks = 0; ks < 4; ks++) {
            int kb = ks * 32;                  // 16 bf16 = 32 bytes
            uint32_t ah[2][4];
            #pragma unroll
            for (int mt = 0; mt < 2; mt++) {
                int row = wm*32 + mt*16 + g;
                int b0 = row*APITCH + kb + tq*4;
                int b1 = (row+8)*APITCH + kb + tq*4;
                ah[mt][0] = *(const uint32_t*)(Ab + b0);
                ah[mt][1] = *(const uint32_t*)(Ab + b1);
                ah[mt][2] = *(const uint32_t*)(Ab + b0 + 16);
                ah[mt][3] = *(const uint32_t*)(Ab + b1 + 16);
            }
            #pragma unroll
            for (int nt = 0; nt < 8; nt++) {
                int coln = wn*64 + nt*8 + g;
                int bb = coln*APITCH + kb + tq*4;
                uint32_t bh0 = *(const uint32_t*)(Bb + bb);
                uint32_t bh1 = *(const uint32_t*)(Bb + bb + 16);
                #pragma unroll
                for (int mt = 0; mt < 2; mt++)
                    mma_bf16(c[mt][nt], ah[mt], bh0, bh1);
            }
        }
    }

    // epilogue: c-frag layout c0=(g,2tq) c1=(g,2tq+1) c2=(g+8,2tq) c3=(g+8,2tq+1)
    #pragma unroll
    for (int mt = 0; mt < 2; mt++) {
        int row = m0 + wm*32 + mt*16 + g;
        #pragma unroll
        for (int nt = 0; nt < 8; nt++) {
            int col = sl*128 + wn*64 + nt*8 + 2*tq;
            float2 v0 = make_float2(c[mt][nt][0], c[mt][nt][1]);
            float2 v1 = make_float2(c[mt][nt][2], c[mt][nt][3]);
            *(float2*)&Y[(size_t)row*ldY + col] = v0;
            *(float2*)&Y[(size_t)(row+8)*ldY + col] = v1;
        }
    }
}

// ---------------- combine conv slices + relu + l2 normalize ----------------
// One warp per sequence position; 4 positions per 128-thread block.
template<int ISD>
__global__ void k_combine(const float* ub, const float* bbias, const float* tb) {
    const float* Y = ISD ? g_Yd : g_Yq;
    float* outU = ISD ? g_du : g_qu;
    float* outB = ISD ? g_db : g_qb;
    float* outT = ISD ? g_dt : g_qt;
    const int L = ISD ? LDV : LQV;

    int idx = blockIdx.x * 4 + (threadIdx.x >> 5);
    int lane = threadIdx.x & 31;
    int l = idx % L;
    int b = idx / L;
    const float* y0 = Y + (size_t)idx * 768;
    bool hasB = (l < L-1), hasT = (l < L-2);

    float u[4], bv[4], tv[4];
    float su = 0.f, sb = 0.f, st = 0.f;
    #pragma unroll
    for (int j = 0; j < 4; j++) {
        int o = lane + 32*j;
        u[j] = fmaxf(y0[o] + ub[o], 0.f);
        su = fmaf(u[j], u[j], su);
        bv[j] = 0.f; tv[j] = 0.f;
        if (hasB) {
            bv[j] = fmaxf(y0[128+o] + y0[768+256+o] + bbias[o], 0.f);
            sb = fmaf(bv[j], bv[j], sb);
        }
        if (hasT) {
            tv[j] = fmaxf(y0[384+o] + y0[768+512+o] + y0[1536+640+o] + tb[o], 0.f);
            st = fmaf(tv[j], tv[j], st);
        }
    }
    su = warp_allreduce(su);
    sb = warp_allreduce(sb);
    st = warp_allreduce(st);
    float iu = 1.f / fmaxf(sqrtf(su), 1e-10f);
    float ib = 1.f / fmaxf(sqrtf(sb), 1e-10f);
    float it = 1.f / fmaxf(sqrtf(st), 1e-10f);
    #pragma unroll
    for (int j = 0; j < 4; j++) {
        int o = lane + 32*j;
        outU[(size_t)idx*128 + o] = u[j] * iu;
        if (hasB) outB[((size_t)b*(L-1) + l)*128 + o] = bv[j] * ib;
        if (hasT) outT[((size_t)b*(L-2) + l)*128 + o] = tv[j] * it;
    }
}

// ---------------- entity branch ----------------
__global__ void k_ent(const int* qei, const int* qew, const int* dei, const int* dew,
                      const float* ent_emb, const float* car_emb, const float* des_b) {
    int x = blockIdx.x;
    bool isQ = x < BB*EQV;
    int o = threadIdx.x;
    int b, e, rowbase, eid;
    const int* carIds; const float* bow;
    if (isQ) {
        b = x / EQV; e = x % EQV;
        rowbase = x * DESCV;
        carIds = qew + b*EQV*KCV + e*KCV;
        eid = qei[b*EQV + e];
        bow = g_bow + (size_t)b*128;
    } else {
        int xi = x - BB*EQV;
        b = xi / EDV; e = xi % EDV;
        rowbase = BB*EQV*DESCV + xi*DESCV;
        carIds = dew + b*EDV*KCV + e*KCV;
        eid = dei[b*EDV + e];
        bow = g_bow + (size_t)(BB + b)*128;
    }
    float bias = des_b[o];
    float mx = 0.f;
    for (int pos = 0; pos < 16; pos++) {
        float sacc = bias;
        #pragma unroll
        for (int i = 0; i < 5; i++)
            sacc += g_Ydesc[(size_t)(rowbase + pos + i)*640 + i*128 + o];
        mx = fmaxf(mx, sacc);
    }
    __shared__ float bs[128];
    __shared__ float tS[10][128];
    __shared__ float sc[10];
    __shared__ float att[10];
    bs[o] = bow[o];
    __syncthreads();
    for (int k = 0; k < 10; k++) {
        float v = car_emb[(size_t)carIds[k]*128 + o];
        tS[k][o] = v;
        float p = block_sum_128(bs[o] * v);
        if (o == 0) sc[k] = p;
    }
    __syncthreads();
    if (o == 0) {
        float m = sc[0];
        #pragma unroll
        for (int k = 1; k < 10; k++) m = fmaxf(m, sc[k]);
        float sum = 0.f;
        #pragma unroll
        for (int k = 0; k < 10; k++) { att[k] = expf(sc[k] - m); sum += att[k]; }
        float inv = 1.f / sum;
        #pragma unroll
        for (int k = 0; k < 10; k++) att[k] *= inv;
    }
    __syncthreads();
    float ew = 0.f;
    #pragma unroll
    for (int k = 0; k < 10; k++) ew = fmaf(att[k], tS[k][o], ew);
    float val = ent_emb[(size_t)eid*128 + o] + mx + ew;
    float nsq = block_sum_128(val * val);
    float nv = val / fmaxf(sqrtf(nsq), 1e-10f);
    if (isQ) g_qs[(size_t)(b*EQV + e)*128 + o] = nv;
    else     g_ds[(size_t)(b*EDV + e)*128 + o] = nv;
}

// ---------------- kernel pooling ----------------
__global__ void __launch_bounds__(256) k_pool(const float* qwm, const float* qem,
                                              const float* dwm, const float* dem) {
    int blk = blockIdx.x;
    int b = blk >> 4, p = blk & 15;
    int qt = c_poolQ[p], dt = c_poolD[p];

    const float* Q; int Lq; const float* mqp;
    switch (qt) {
        case 0: Q = g_qu + (size_t)b*20*128; Lq = 20; mqp = qwm + b*LQV; break;
        case 1: Q = g_qb + (size_t)b*19*128; Lq = 19; mqp = qwm + b*LQV; break;
        case 2: Q = g_qt + (size_t)b*18*128; Lq = 18; mqp = qwm + b*LQV; break;
        default:Q = g_qs + (size_t)b*5*128;  Lq = 5;  mqp = qem + b*EQV; break;
    }
    const float* Dp; int Ld; const float* mdp;
    switch (dt) {
        case 0: Dp = g_du + (size_t)b*512*128; Ld = 512; mdp = dwm + b*LDV; break;
        case 1: Dp = g_db + (size_t)b*511*128; Ld = 511; mdp = dwm + b*LDV; break;
        case 2: Dp = g_dt + (size_t)b*510*128; Ld = 510; mdp = dwm + b*LDV; break;
        default:Dp = g_ds + (size_t)b*10*128;  Ld = 10;  mdp = dem + b*EDV; break;
    }

    __shared__ float Qs[20][132];
    __shared__ float DtS[128][36];
    __shared__ float simS[20][36];
    __shared__ float mdS[32];
    __shared__ float lpsS[20*11];

    int t = threadIdx.x;
    for (int e = t; e < Lq*128; e += 256) { int q = e >> 7, k = e & 127; Qs[q][k] = Q[e]; }

    int myq = t / 11, myk = t % 11;
    bool active = t < Lq * 11;
    float mu_ = c_MU[myk], is2 = c_IS2[myk];
    float acc = 0.f;

    for (int cc0 = 0; cc0 < Ld; cc0 += 32) {
        int cn = min(32, Ld - cc0);
        __syncthreads();
        for (int e = t; e < cn*128; e += 256) {
            int cc = e >> 7, k = e & 127;
            DtS[k][cc] = Dp[(size_t)(cc0 + cc)*128 + k];
        }
        if (t < cn) mdS[t] = mdp[cc0 + t];
        __syncthreads();
        int ncg = (cn + 3) >> 2;
        for (int mt = t; mt < Lq*8; mt += 256) {
            int q = mt >> 3, cg = mt & 7;
            if (cg < ncg) {
                float s0 = 0.f, s1 = 0.f, s2 = 0.f, s3 = 0.f;
                const float* qrow = &Qs[q][0];
                #pragma unroll 4
                for (int kk = 0; kk < 128; kk++) {
                    float qa = qrow[kk];
                    float4 d4 = *(const float4*)&DtS[kk][cg << 2];
                    s0 = fmaf(qa, d4.x, s0);
                    s1 = fmaf(qa, d4.y, s1);
                    s2 = fmaf(qa, d4.z, s2);
                    s3 = fmaf(qa, d4.w, s3);
                }
                int cb = cg << 2;
                simS[q][cb] = s0; simS[q][cb+1] = s1; simS[q][cb+2] = s2; simS[q][cb+3] = s3;
            }
        }
        __syncthreads();
        if (active) {
            const float* srow = &simS[myq][0];
            for (int cc = 0; cc < cn; cc++) {
                float df = srow[cc] - mu_;
                acc = fmaf(mdS[cc], __expf(-df*df*is2), acc);
            }
        }
    }
    __syncthreads();
    if (active)
        lpsS[myq*11 + myk] = logf(fmaxf(acc, 1e-10f)) * 0.01f * mqp[myq];
    __syncthreads();
    if (t < 11) {
        float s = 0.f;
        for (int q = 0; q < Lq; q++) s += lpsS[q*11 + t];
        g_feats[b*176 + p*11 + t] = s;
    }
}

// ---------------- final dense + tanh ----------------
__global__ void k_final(const float* W, const float* b0, float* out) {
    int b = threadIdx.x;
    if (b < BB) {
        float s = b0[0];
        #pragma unroll 4
        for (int j = 0; j < 176; j++) s = fmaf(g_feats[b*176 + j], W[j], s);
        out[b] = tanhf(s);
    }
}

// ---------------- launch ----------------
extern "C" void kernel_launch(void* const* d_in, const int* in_sizes, int n_in,
                              void* d_out, int out_size) {
    const int*   qwt  = (const int*)  d_in[0];
    const float* qwm  = (const float*)d_in[1];
    const int*   qei  = (const int*)  d_in[2];
    const int*   qet  = (const int*)  d_in[3];
    const int*   qew  = (const int*)  d_in[4];
    const float* qem  = (const float*)d_in[5];
    const int*   dwt  = (const int*)  d_in[6];
    const float* dwm  = (const float*)d_in[7];
    const int*   dei  = (const int*)  d_in[8];
    const int*   det  = (const int*)  d_in[9];
    const int*   dew  = (const int*)  d_in[10];
    const float* dem  = (const float*)d_in[11];
    const float* wrd  = (const float*)d_in[12];
    const float* ente = (const float*)d_in[13];
    const float* care = (const float*)d_in[14];
    const float* bowW = (const float*)d_in[15];
    const float* bowb = (const float*)d_in[16];
    const float* uW   = (const float*)d_in[17];
    const float* ub   = (const float*)d_in[18];
    const float* bW   = (const float*)d_in[19];
    const float* bb   = (const float*)d_in[20];
    const float* tW   = (const float*)d_in[21];
    const float* tb   = (const float*)d_in[22];
    const float* dW   = (const float*)d_in[23];
    const float* db_  = (const float*)d_in[24];
    const float* fW   = (const float*)d_in[25];
    const float* fb   = (const float*)d_in[26];
    float* out = (float*)d_out;

    cudaFuncSetAttribute(k_gemm_mma, cudaFuncAttributeMaxDynamicSharedMemorySize, SMEM_DYN);

    k_prep_weights<<<240, 256>>>(uW, bW, tW, dW);
    k_prep_emb<<<4096, 256>>>(wrd);
    k_sum_part<<<dim3(BB, 2, 4), 320>>>(qwt, dwt, wrd);
    k_bow<<<dim3(BB, 2), 128>>>(bowW, bowb);

    k_gemm_mma<<<TB_ALL, 256, SMEM_DYN>>>(qwt, dwt, qet, det);

    k_combine<0><<<BB*LQV/4, 128>>>(ub, bb, tb);
    k_combine<1><<<BB*LDV/4, 128>>>(ub, bb, tb);

    k_ent<<<BB*(EQV + EDV), 128>>>(qei, qew, dei, dew, ente, care, db_);
    k_pool<<<BB*16, 256>>>(qwm, qem, dwm, dem);
    k_final<<<1, 64>>>(fW, fb, out);
}